// round 12
// baseline (speedup 1.0000x reference)
#include <cuda_runtime.h>
#include <cuda_bf16.h>
#include <math.h>

#define ME   128
#define MN   128
#define NDET 32
#define NO   (NDET*ME)
#define LOG2E 1.4426950408889634f
#define NBLK 296          // 2 blocks/SM * 148 SMs -> one wave
#define BPS  148

#define ROWP 132          // padded row: stride = 4 banks -> conflict-free
#define OFF_SZL (ME*ROWP)
#define OFF_SPI (OFF_SZL + 28*ROWP)
#define OFF_SFE (OFF_SPI + 28*ROWP)
#define OFF_SNC (OFF_SFE + 128*4)
#define OFF_SEC (OFF_SNC + 128*4)
#define SMEM_FLOATS (OFF_SEC + 128*4)   // 103296 B; 2 blocks/SM

#define A_ORB 21          // rows 0..20 -> MUFU warps (0-3)
#define B_ORB 7           // rows 21..27 -> poly warps (4-7); 25% of work

__device__ __forceinline__ float ex2(float x) {
    float y; asm("ex2.approx.ftz.f32 %0, %1;" : "=f"(y) : "f"(x)); return y;
}
__device__ __forceinline__ float sqrt_fma(float x) {
    x = fmaxf(x, 1e-20f);
    float y = __int_as_float(0x5f3759df - (__float_as_int(x) >> 1));
    float nh = -0.5f * x;
    y = y * fmaf(nh, y * y, 1.5f);
    y = y * fmaf(nh, y * y, 1.5f);
    return x * y;
}

// ---- packed f32x2 helpers (sm_103a) ----
typedef unsigned long long u64;
__device__ __forceinline__ u64 pk2(float lo, float hi) {
    u64 r;
    asm("mov.b64 %0, {%1, %2};" : "=l"(r) : "r"(__float_as_uint(lo)), "r"(__float_as_uint(hi)));
    return r;
}
__device__ __forceinline__ void unpk2(float& lo, float& hi, u64 v) {
    unsigned a, b;
    asm("mov.b64 {%0, %1}, %2;" : "=r"(a), "=r"(b) : "l"(v));
    lo = __uint_as_float(a); hi = __uint_as_float(b);
}
__device__ __forceinline__ u64 add2(u64 a, u64 b) {
    u64 r; asm("add.rn.f32x2 %0, %1, %2;" : "=l"(r) : "l"(a), "l"(b)); return r;
}
__device__ __forceinline__ u64 mul2(u64 a, u64 b) {
    u64 r; asm("mul.rn.f32x2 %0, %1, %2;" : "=l"(r) : "l"(a), "l"(b)); return r;
}
__device__ __forceinline__ u64 fma2(u64 a, u64 b, u64 c) {
    u64 r; asm("fma.rn.f32x2 %0, %1, %2, %3;" : "=l"(r) : "l"(a), "l"(b), "l"(c)); return r;
}

struct PolyConst { u64 M2, MN2, NEG1, C3, C2, C1, C0; };

// exp2 on a packed pair via FMA pipe; accumulate pi*exp into packed acc.
__device__ __forceinline__ void poly_pair(float d0, float d1, float z0, float z1,
                                          float p0, float p1, u64& acc,
                                          const PolyConst& K) {
    float x0 = fmaxf(d0 * z0, -125.0f);
    float x1 = fmaxf(d1 * z1, -125.0f);
    u64 X  = pk2(x0, x1);
    u64 Y  = add2(X, K.M2);          // magic: n = round(x) in low bits
    u64 FN = add2(Y, K.MN2);         // fn = n as float
    u64 F  = fma2(FN, K.NEG1, X);    // f = x - fn, f in [-0.5,0.5]
    u64 P  = fma2(F, K.C3, K.C2);
    P = fma2(P, F, K.C1);
    P = fma2(P, F, K.C0);
    float y0, y1; unpk2(y0, y1, Y);
    float s0 = __uint_as_float(__float_as_uint(y0) * 8388608u + 0x3F800000u);  // 2^n
    float s1 = __uint_as_float(__float_as_uint(y1) * 8388608u + 0x3F800000u);
    u64 E  = mul2(pk2(s0, s1), P);
    acc = fma2(pk2(p0, p1), E, acc);
}

__device__ __forceinline__ unsigned char mask_val(const unsigned char* p, int i, int mode) {
    if (mode == 2) return (((const float*)p)[i] != 0.0f);
    if (mode == 1) return (((const int*)p)[i] != 0);
    if (mode == 3) return 0;
    return (p[i] != 0);
}

__global__ void __launch_bounds__(256, 2) k_fused(
        const float* __restrict__ up, const float* __restrict__ dn,
        const float* __restrict__ nc, const float* __restrict__ q,
        const float* __restrict__ Wpu, const float* __restrict__ Wzu,
        const float* __restrict__ Wpd, const float* __restrict__ Wzd,
        const unsigned char* __restrict__ um, const unsigned char* __restrict__ dm,
        const unsigned char* __restrict__ nm, float* __restrict__ out) {
    extern __shared__ float smem[];
    float* sd  = smem;
    float* szl = smem + OFF_SZL;
    float* spi = smem + OFF_SPI;
    float* sfe = smem + OFF_SFE;
    float* snc = smem + OFF_SNC;
    float* sec = smem + OFF_SEC;
    __shared__ int   smode[2];
    __shared__ float spart[4][4];
    __shared__ unsigned char sem[128];
    __shared__ unsigned char snm[128];
    __shared__ float smean[3];

    int bx  = blockIdx.x;
    int s   = (bx >= BPS) ? 1 : 0;
    int bl  = bx - s * BPS;
    int tid = threadIdx.x;
    int lane = tid & 31;

    int o_start = (bl * NO) / BPS;       // ragged 27/28-orbital range
    int ow      = ((bl + 1) * NO) / BPS - o_start;

    const float* ec = s ? dn : up;
    const float* Wp = s ? Wpd : Wpu;     // zeta from W_pi
    const float* Wz = s ? Wzd : Wzu;     // pi from W_zeta
    const unsigned char* emp = s ? dm : um;

    // --- mask-mode detection (ballot, warps 0 and 4) ---
    if (tid < 32 || (tid >= 128 && tid < 160)) {
        const unsigned char* p = (tid < 32) ? emp : nm;
        unsigned int w = ((const unsigned int*)p)[lane];
        unsigned int ex = w & 0x7F800000u;
        bool isf = (w == 0x3F800000u) || (ex >= 0x38000000u && ex <= 0x47000000u);
        unsigned anyF  = __ballot_sync(0xFFFFFFFFu, isf);
        unsigned anyNZ = __ballot_sync(0xFFFFFFFFu, w != 0u);
        unsigned small = __ballot_sync(0xFFFFFFFFu, w <= 1u);
        if (lane == 0) {
            int mode;
            if (!anyNZ)                     mode = 3;
            else if (anyF)                  mode = 2;
            else if (small == 0xFFFFFFFFu)  mode = 1;
            else                            mode = 0;
            smode[tid < 32 ? 0 : 1] = mode;
        }
    }
    __syncthreads();
    if (tid < 128)       sem[tid]       = mask_val(emp, tid, smode[0]);
    else                 snm[tid - 128] = mask_val(nm, tid - 128, smode[1]);
    __syncthreads();

    // --- coords + masked mean via warp shuffles ---
    if (tid < 128) {
        float m = snm[tid] ? 1.0f : 0.0f;
        float x = nc[3*tid+0], y = nc[3*tid+1], z = nc[3*tid+2];
        snc[4*tid+0] = x; snc[4*tid+1] = y; snc[4*tid+2] = z; snc[4*tid+3] = m;
        sec[4*tid+0] = ec[3*tid+0]; sec[4*tid+1] = ec[3*tid+1]; sec[4*tid+2] = ec[3*tid+2];
        float xm = x * m, ym = y * m, zm = z * m, cm = m;
        #pragma unroll
        for (int off = 16; off > 0; off >>= 1) {
            xm += __shfl_down_sync(0xFFFFFFFFu, xm, off);
            ym += __shfl_down_sync(0xFFFFFFFFu, ym, off);
            zm += __shfl_down_sync(0xFFFFFFFFu, zm, off);
            cm += __shfl_down_sync(0xFFFFFFFFu, cm, off);
        }
        if (lane == 0) {
            int w = tid >> 5;
            spart[w][0] = xm; spart[w][1] = ym; spart[w][2] = zm; spart[w][3] = cm;
        }
    }
    __syncthreads();
    if (tid == 0) {
        float x = spart[0][0] + spart[1][0] + spart[2][0] + spart[3][0];
        float y = spart[0][1] + spart[1][1] + spart[2][1] + spart[3][1];
        float z = spart[0][2] + spart[1][2] + spart[2][2] + spart[3][2];
        float c = fmaxf(spart[0][3] + spart[1][3] + spart[2][3] + spart[3][3], 1.0f);
        smean[0] = x / c; smean[1] = y / c; smean[2] = z / c;
    }
    __syncthreads();
    if (tid < 128) {
        float m = snc[4*tid+3];
        sfe[4*tid+0] = q[tid] * m;
        sfe[4*tid+1] = (snc[4*tid+0] - smean[0]) * m;
        sfe[4*tid+2] = (snc[4*tid+1] - smean[1]) * m;
        sfe[4*tid+3] = (snc[4*tid+2] - smean[2]) * m;
    }

    // --- dist tile [128 e][128 n] (sqrt on FMA/ALU pipes) ---
    #pragma unroll
    for (int i = tid; i < ME * MN; i += 256) {
        int e = i >> 7, n = i & 127;
        float dx = sec[4*e+0] - snc[4*n+0];
        float dy = sec[4*e+1] - snc[4*n+1];
        float dz = sec[4*e+2] - snc[4*n+2];
        sd[e * ROWP + n] = sqrt_fma(fmaf(dx, dx, fmaf(dy, dy, dz*dz)));
    }
    __syncthreads();

    // --- single 28-row zl/pi fill (invalid row zero-padded) ---
    #pragma unroll
    for (int j = tid; j < 28 * MN; j += 256) {
        int ol = j >> 7, n = j & 127;
        int o  = o_start + ol;
        float zl = 0.0f, pi = 0.0f;
        if (ol < ow) {
            float f0 = sfe[4*n+0], f1 = sfe[4*n+1], f2 = sfe[4*n+2], f3 = sfe[4*n+3];
            float zeta = fmaf(f0, Wp[o], fmaf(f1, Wp[NO+o], fmaf(f2, Wp[2*NO+o], f3 * Wp[3*NO+o])));
            pi   = fmaf(f0, Wz[o], fmaf(f1, Wz[NO+o], fmaf(f2, Wz[2*NO+o], f3 * Wz[3*NO+o])));
            zl   = -fabsf(zeta) * LOG2E;
        }
        szl[ol * ROWP + n] = zl;
        spi[ol * ROWP + n] = pi;
    }
    __syncthreads();   // last barrier — roles diverge below

    if (tid < 128) {
        // ===== A role (warps 0-3, one per SMSP): pure MUFU, rows 0..20 =====
        const int e = tid;
        float acc[A_ORB];
        #pragma unroll
        for (int i = 0; i < A_ORB; i++) acc[i] = 0.0f;
        const float* sd0 = sd + e * ROWP;
        #pragma unroll 1
        for (int c = 0; c < 32; c++) {
            float4 d = *(const float4*)(sd0 + c * 4);
            #pragma unroll
            for (int ol = 0; ol < A_ORB; ol++) {
                float4 z = *(const float4*)(szl + ol * ROWP + c * 4);
                float4 p = *(const float4*)(spi + ol * ROWP + c * 4);
                float a = acc[ol];
                a = fmaf(p.x, ex2(d.x * z.x), a);
                a = fmaf(p.y, ex2(d.y * z.y), a);
                a = fmaf(p.z, ex2(d.z * z.z), a);
                a = fmaf(p.w, ex2(d.w * z.w), a);
                acc[ol] = a;
            }
        }
        bool eok = (sem[e] != 0);
        #pragma unroll
        for (int ol = 0; ol < A_ORB; ol++) {
            int o = o_start + ol;
            int d = o >> 7, m = o & 127;
            float v = (eok && (sem[m] != 0)) ? acc[ol] : (e == m ? 1.0f : 0.0f);
            out[(((s << 5) + d) << 14) + (e << 7) + m] = v;
        }
    } else {
        // ===== B role (warps 4-7): packed-poly on FMA pipe, rows 21..27 =====
        const int e = tid - 128;
        PolyConst K;
        K.M2   = pk2( 12582912.0f,  12582912.0f);
        K.MN2  = pk2(-12582912.0f, -12582912.0f);
        K.NEG1 = pk2(-1.0f, -1.0f);
        K.C3   = pk2(0.0555041f, 0.0555041f);
        K.C2   = pk2(0.2426315f, 0.2426315f);
        K.C1   = pk2(0.6931472f, 0.6931472f);
        K.C0   = pk2(0.9999249f, 0.9999249f);
        u64 acc[B_ORB];
        #pragma unroll
        for (int i = 0; i < B_ORB; i++) acc[i] = pk2(0.0f, 0.0f);
        const float* sd0 = sd + e * ROWP;
        #pragma unroll 1
        for (int c = 0; c < 32; c++) {
            float4 d = *(const float4*)(sd0 + c * 4);
            #pragma unroll
            for (int ol = 0; ol < B_ORB; ol++) {
                float4 z = *(const float4*)(szl + (A_ORB + ol) * ROWP + c * 4);
                float4 p = *(const float4*)(spi + (A_ORB + ol) * ROWP + c * 4);
                poly_pair(d.x, d.y, z.x, z.y, p.x, p.y, acc[ol], K);
                poly_pair(d.z, d.w, z.z, z.w, p.z, p.w, acc[ol], K);
            }
        }
        bool eok = (sem[e] != 0);
        int cw = ow - A_ORB;   // 6 or 7 valid B rows
        #pragma unroll
        for (int ol = 0; ol < B_ORB; ol++) {
            if (ol < cw) {
                float lo, hi; unpk2(lo, hi, acc[ol]);
                int o = o_start + A_ORB + ol;
                int d = o >> 7, m = o & 127;
                float v = (eok && (sem[m] != 0)) ? (lo + hi) : (e == m ? 1.0f : 0.0f);
                out[(((s << 5) + d) << 14) + (e << 7) + m] = v;
            }
        }
    }
}

// ---------------------------------------------------------------------------
extern "C" void kernel_launch(void* const* d_in, const int* in_sizes, int n_in,
                              void* d_out, int out_size) {
    const float* up  = (const float*)d_in[0];
    const float* dn  = (const float*)d_in[1];
    const float* nc  = (const float*)d_in[2];
    const float* q   = (const float*)d_in[3];
    const float* Wpu = (const float*)d_in[4];
    const float* Wzu = (const float*)d_in[5];
    const float* Wpd = (const float*)d_in[6];
    const float* Wzd = (const float*)d_in[7];
    const unsigned char* um = (const unsigned char*)d_in[8];
    const unsigned char* dm = (const unsigned char*)d_in[9];
    const unsigned char* nm = (const unsigned char*)d_in[10];
    float* out = (float*)d_out;

    cudaFuncSetAttribute(k_fused, cudaFuncAttributeMaxDynamicSharedMemorySize,
                         SMEM_FLOATS * sizeof(float));
    k_fused<<<NBLK, 256, SMEM_FLOATS * sizeof(float)>>>(
        up, dn, nc, q, Wpu, Wzu, Wpd, Wzd, um, dm, nm, out);
}

// round 13
// speedup vs baseline: 1.2039x; 1.2039x over previous
#include <cuda_runtime.h>
#include <cuda_bf16.h>
#include <math.h>

#define ME   128
#define MN   128
#define NDET 32
#define NO   (NDET*ME)
#define LOG2E 1.4426950408889634f
#define NBLK 296          // 2 blocks/SM * 148 SMs -> exactly one wave
#define BPS  148

#define ROWP 132          // padded row: stride = 4 banks -> conflict-free LDS.128
#define OFF_SZL (ME*ROWP)
#define OFF_SPI (OFF_SZL + 16*ROWP)
#define OFF_SFE (OFF_SPI + 16*ROWP)
#define OFF_SNC (OFF_SFE + 128*4)
#define OFF_SEC (OFF_SNC + 128*4)
#define SMEM_FLOATS (OFF_SEC + 128*4)   // 90624 B -> 2 blocks/SM

__device__ __forceinline__ float ex2(float x) {
    float y; asm("ex2.approx.ftz.f32 %0, %1;" : "=f"(y) : "f"(x)); return y;
}

// All-FMA/ALU sqrt: Quake rsqrt seed + 2 Newton iters (rel err ~3e-9).
// Keeps dist-tile work off MUFU (the binding pipe).
__device__ __forceinline__ float sqrt_fma(float x) {
    x = fmaxf(x, 1e-20f);
    float y = __int_as_float(0x5f3759df - (__float_as_int(x) >> 1));
    float nh = -0.5f * x;
    y = y * fmaf(nh, y * y, 1.5f);
    y = y * fmaf(nh, y * y, 1.5f);
    return x * y;
}

__device__ __forceinline__ unsigned char mask_val(const unsigned char* p, int i, int mode) {
    if (mode == 2) return (((const float*)p)[i] != 0.0f);
    if (mode == 1) return (((const int*)p)[i] != 0);
    if (mode == 3) return 0;
    return (p[i] != 0);
}

__global__ void __launch_bounds__(256, 2) k_fused(
        const float* __restrict__ up, const float* __restrict__ dn,
        const float* __restrict__ nc, const float* __restrict__ q,
        const float* __restrict__ Wpu, const float* __restrict__ Wzu,
        const float* __restrict__ Wpd, const float* __restrict__ Wzd,
        const unsigned char* __restrict__ um, const unsigned char* __restrict__ dm,
        const unsigned char* __restrict__ nm, float* __restrict__ out) {
    extern __shared__ float smem[];
    float* sd  = smem;
    float* szl = smem + OFF_SZL;
    float* spi = smem + OFF_SPI;
    float* sfe = smem + OFF_SFE;
    float* snc = smem + OFF_SNC;
    float* sec = smem + OFF_SEC;
    __shared__ int   smode[2];
    __shared__ float spart[4][4];        // warp partial sums: x,y,z,cnt
    __shared__ unsigned char sem[128];
    __shared__ unsigned char snm[128];
    __shared__ float smean[3];

    int bx  = blockIdx.x;
    int s   = (bx >= BPS) ? 1 : 0;
    int bl  = bx - s * BPS;
    int tid = threadIdx.x;
    int lane = tid & 31;

    int o_start = (bl * NO) / BPS;       // ragged 27/28-orbital range
    int o_end   = ((bl + 1) * NO) / BPS;

    const float* ec = s ? dn : up;
    const float* Wp = s ? Wpd : Wpu;     // zeta from W_pi
    const float* Wz = s ? Wzd : Wzu;     // pi from W_zeta
    const unsigned char* emp = s ? dm : um;

    // --- mask-mode detection: one warp per mask, ballot-based (no loop) ---
    if (tid < 32 || (tid >= 128 && tid < 160)) {
        const unsigned char* p = (tid < 32) ? emp : nm;
        unsigned int w = ((const unsigned int*)p)[lane];
        unsigned int ex = w & 0x7F800000u;
        bool isf = (w == 0x3F800000u) || (ex >= 0x38000000u && ex <= 0x47000000u);
        unsigned anyF  = __ballot_sync(0xFFFFFFFFu, isf);
        unsigned anyNZ = __ballot_sync(0xFFFFFFFFu, w != 0u);
        unsigned small = __ballot_sync(0xFFFFFFFFu, w <= 1u);
        if (lane == 0) {
            int mode;
            if (!anyNZ)                     mode = 3;
            else if (anyF)                  mode = 2;
            else if (small == 0xFFFFFFFFu)  mode = 1;
            else                            mode = 0;
            smode[tid < 32 ? 0 : 1] = mode;
        }
    }
    __syncthreads();
    if (tid < 128)       sem[tid]       = mask_val(emp, tid, smode[0]);
    else                 snm[tid - 128] = mask_val(nm, tid - 128, smode[1]);
    __syncthreads();

    // --- stage coords; masked mean via warp shuffles (2 barriers total) ---
    if (tid < 128) {
        float m = snm[tid] ? 1.0f : 0.0f;
        float x = nc[3*tid+0], y = nc[3*tid+1], z = nc[3*tid+2];
        snc[4*tid+0] = x; snc[4*tid+1] = y; snc[4*tid+2] = z; snc[4*tid+3] = m;
        sec[4*tid+0] = ec[3*tid+0]; sec[4*tid+1] = ec[3*tid+1]; sec[4*tid+2] = ec[3*tid+2];
        float xm = x * m, ym = y * m, zm = z * m, cm = m;
        #pragma unroll
        for (int off = 16; off > 0; off >>= 1) {
            xm += __shfl_down_sync(0xFFFFFFFFu, xm, off);
            ym += __shfl_down_sync(0xFFFFFFFFu, ym, off);
            zm += __shfl_down_sync(0xFFFFFFFFu, zm, off);
            cm += __shfl_down_sync(0xFFFFFFFFu, cm, off);
        }
        if (lane == 0) {
            int w = tid >> 5;
            spart[w][0] = xm; spart[w][1] = ym; spart[w][2] = zm; spart[w][3] = cm;
        }
    }
    __syncthreads();
    if (tid == 0) {
        float x = spart[0][0] + spart[1][0] + spart[2][0] + spart[3][0];
        float y = spart[0][1] + spart[1][1] + spart[2][1] + spart[3][1];
        float z = spart[0][2] + spart[1][2] + spart[2][2] + spart[3][2];
        float c = fmaxf(spart[0][3] + spart[1][3] + spart[2][3] + spart[3][3], 1.0f);
        smean[0] = x / c; smean[1] = y / c; smean[2] = z / c;
    }
    __syncthreads();
    if (tid < 128) {
        float m = snc[4*tid+3];
        sfe[4*tid+0] = q[tid] * m;
        sfe[4*tid+1] = (snc[4*tid+0] - smean[0]) * m;
        sfe[4*tid+2] = (snc[4*tid+1] - smean[1]) * m;
        sfe[4*tid+3] = (snc[4*tid+2] - smean[2]) * m;
    }

    // --- dist tile [128 e][128 n] (sqrt on FMA/ALU pipes) ---
    #pragma unroll
    for (int i = tid; i < ME * MN; i += 256) {
        int e = i >> 7, n = i & 127;
        float dx = sec[4*e+0] - snc[4*n+0];
        float dy = sec[4*e+1] - snc[4*n+1];
        float dz = sec[4*e+2] - snc[4*n+2];
        sd[e * ROWP + n] = sqrt_fma(fmaf(dx, dx, fmaf(dy, dy, dz*dz)));
    }
    __syncthreads();   // sfe + sd ready

    // ========== chunk 0: 16 orbitals at o_start ==========
    #pragma unroll
    for (int j = tid; j < 16 * MN; j += 256) {
        int ol = j >> 7, n = j & 127;
        int o  = o_start + ol;
        float f0 = sfe[4*n+0], f1 = sfe[4*n+1], f2 = sfe[4*n+2], f3 = sfe[4*n+3];
        float zeta = fmaf(f0, Wp[o], fmaf(f1, Wp[NO+o], fmaf(f2, Wp[2*NO+o], f3 * Wp[3*NO+o])));
        float pi   = fmaf(f0, Wz[o], fmaf(f1, Wz[NO+o], fmaf(f2, Wz[2*NO+o], f3 * Wz[3*NO+o])));
        szl[ol * ROWP + n] = -fabsf(zeta) * LOG2E;
        spi[ol * ROWP + n] = pi;
    }
    __syncthreads();

    {   // map A: 4e x 2o per thread (pure MUFU — proven optimal)
        int eg = tid >> 3, og = tid & 7;
        float acc[4][2];
        #pragma unroll
        for (int ei = 0; ei < 4; ei++)
            #pragma unroll
            for (int oj = 0; oj < 2; oj++) acc[ei][oj] = 0.0f;
        const float* sd0 = sd  + eg * ROWP;
        const float* z0  = szl + og * ROWP;
        const float* p0  = spi + og * ROWP;
        #pragma unroll 4
        for (int c = 0; c < 32; c++) {
            float4 d0 = *(const float4*)(sd0 +  0 * ROWP + c * 4);
            float4 d1 = *(const float4*)(sd0 + 32 * ROWP + c * 4);
            float4 d2 = *(const float4*)(sd0 + 64 * ROWP + c * 4);
            float4 d3 = *(const float4*)(sd0 + 96 * ROWP + c * 4);
            #pragma unroll
            for (int oj = 0; oj < 2; oj++) {
                float4 z = *(const float4*)(z0 + oj * 8 * ROWP + c * 4);
                float4 p = *(const float4*)(p0 + oj * 8 * ROWP + c * 4);
                float4 dd[4] = {d0, d1, d2, d3};
                #pragma unroll
                for (int ei = 0; ei < 4; ei++) {
                    float a = acc[ei][oj];
                    a = fmaf(p.x, ex2(dd[ei].x * z.x), a);
                    a = fmaf(p.y, ex2(dd[ei].y * z.y), a);
                    a = fmaf(p.z, ex2(dd[ei].z * z.z), a);
                    a = fmaf(p.w, ex2(dd[ei].w * z.w), a);
                    acc[ei][oj] = a;
                }
            }
        }
        #pragma unroll
        for (int ei = 0; ei < 4; ei++) {
            int e = eg + 32 * ei;
            bool eok = (sem[e] != 0);
            #pragma unroll
            for (int oj = 0; oj < 2; oj++) {
                int o = o_start + og + 8 * oj;
                int d = o >> 7, m = o & 127;
                float v = (eok && (sem[m] != 0)) ? acc[ei][oj]
                                                 : (e == m ? 1.0f : 0.0f);
                out[(((s << 5) + d) << 14) + (e << 7) + m] = v;
            }
        }
    }
    __syncthreads();

    // ========== chunk 1: up to 12 orbitals at o_start+16 ==========
    int cw = o_end - (o_start + 16);
    #pragma unroll
    for (int j = tid; j < 12 * MN; j += 256) {
        int ol = j >> 7, n = j & 127;
        int o  = o_start + 16 + ol;
        float zl = 0.0f, pi = 0.0f;
        if (ol < cw) {
            float f0 = sfe[4*n+0], f1 = sfe[4*n+1], f2 = sfe[4*n+2], f3 = sfe[4*n+3];
            float zeta = fmaf(f0, Wp[o], fmaf(f1, Wp[NO+o], fmaf(f2, Wp[2*NO+o], f3 * Wp[3*NO+o])));
            pi   = fmaf(f0, Wz[o], fmaf(f1, Wz[NO+o], fmaf(f2, Wz[2*NO+o], f3 * Wz[3*NO+o])));
            zl   = -fabsf(zeta) * LOG2E;
        }
        szl[ol * ROWP + n] = zl;
        spi[ol * ROWP + n] = pi;
    }
    __syncthreads();

    {   // map B: 2e x 3o per thread (pure MUFU)
        int eg2 = tid >> 2, og2 = tid & 3;
        float acc[2][3];
        #pragma unroll
        for (int ei = 0; ei < 2; ei++)
            #pragma unroll
            for (int oj = 0; oj < 3; oj++) acc[ei][oj] = 0.0f;
        const float* sd0 = sd  + eg2 * ROWP;
        const float* z0  = szl + og2 * ROWP;
        const float* p0  = spi + og2 * ROWP;
        #pragma unroll 4
        for (int c = 0; c < 32; c++) {
            float4 d0 = *(const float4*)(sd0 +  0 * ROWP + c * 4);
            float4 d1 = *(const float4*)(sd0 + 64 * ROWP + c * 4);
            #pragma unroll
            for (int oj = 0; oj < 3; oj++) {
                float4 z = *(const float4*)(z0 + oj * 4 * ROWP + c * 4);
                float4 p = *(const float4*)(p0 + oj * 4 * ROWP + c * 4);
                float4 dd[2] = {d0, d1};
                #pragma unroll
                for (int ei = 0; ei < 2; ei++) {
                    float a = acc[ei][oj];
                    a = fmaf(p.x, ex2(dd[ei].x * z.x), a);
                    a = fmaf(p.y, ex2(dd[ei].y * z.y), a);
                    a = fmaf(p.z, ex2(dd[ei].z * z.z), a);
                    a = fmaf(p.w, ex2(dd[ei].w * z.w), a);
                    acc[ei][oj] = a;
                }
            }
        }
        #pragma unroll
        for (int ei = 0; ei < 2; ei++) {
            int e = eg2 + 64 * ei;
            bool eok = (sem[e] != 0);
            #pragma unroll
            for (int oj = 0; oj < 3; oj++) {
                int ol = og2 + 4 * oj;
                if (ol < cw) {
                    int o = o_start + 16 + ol;
                    int d = o >> 7, m = o & 127;
                    float v = (eok && (sem[m] != 0)) ? acc[ei][oj]
                                                     : (e == m ? 1.0f : 0.0f);
                    out[(((s << 5) + d) << 14) + (e << 7) + m] = v;
                }
            }
        }
    }
}

// ---------------------------------------------------------------------------
extern "C" void kernel_launch(void* const* d_in, const int* in_sizes, int n_in,
                              void* d_out, int out_size) {
    const float* up  = (const float*)d_in[0];
    const float* dn  = (const float*)d_in[1];
    const float* nc  = (const float*)d_in[2];
    const float* q   = (const float*)d_in[3];
    const float* Wpu = (const float*)d_in[4];
    const float* Wzu = (const float*)d_in[5];
    const float* Wpd = (const float*)d_in[6];
    const float* Wzd = (const float*)d_in[7];
    const unsigned char* um = (const unsigned char*)d_in[8];
    const unsigned char* dm = (const unsigned char*)d_in[9];
    const unsigned char* nm = (const unsigned char*)d_in[10];
    float* out = (float*)d_out;

    cudaFuncSetAttribute(k_fused, cudaFuncAttributeMaxDynamicSharedMemorySize,
                         SMEM_FLOATS * sizeof(float));
    k_fused<<<NBLK, 256, SMEM_FLOATS * sizeof(float)>>>(
        up, dn, nc, q, Wpu, Wzu, Wpd, Wzd, um, dm, nm, out);
}